// round 1
// baseline (speedup 1.0000x reference)
#include <cuda_runtime.h>
#include <math.h>

#define BB   2
#define LL   2048
#define DD   1024
#define HH   16
#define DHD  64
#define HID  4096
#define ROWS (BB*LL)          // 4096
#define WIN  256
#define DIL  2

// ---------------- scratch (static device globals; no runtime alloc) ----------
__device__ float g_xn  [ROWS * DD];        // 16 MB
__device__ float g_qkv [ROWS * 3 * DD];    // 48 MB
__device__ float g_attn[ROWS * DD];        // 16 MB
__device__ float g_y   [ROWS * DD];        // 16 MB
__device__ float g_h   [ROWS * DD];        // 16 MB
__device__ float g_ffn [ROWS * HID];       // 64 MB

// ---------------- LayerNorm: one block (256 thr) per row of 1024 -------------
__global__ __launch_bounds__(256)
void ln_kernel(const float* __restrict__ x, const float* __restrict__ w,
               const float* __restrict__ b, float* __restrict__ out)
{
    int row = blockIdx.x;
    int tid = threadIdx.x;
    const float4* xr = reinterpret_cast<const float4*>(x + (size_t)row * DD);
    float4 v = xr[tid];

    float s  = v.x + v.y + v.z + v.w;
    float sq = v.x*v.x + v.y*v.y + v.z*v.z + v.w*v.w;

    __shared__ float sh_s[8], sh_q[8];
    #pragma unroll
    for (int o = 16; o; o >>= 1) {
        s  += __shfl_xor_sync(0xffffffffu, s,  o);
        sq += __shfl_xor_sync(0xffffffffu, sq, o);
    }
    int warp = tid >> 5, lane = tid & 31;
    if (lane == 0) { sh_s[warp] = s; sh_q[warp] = sq; }
    __syncthreads();
    if (warp == 0) {
        s  = sh_s[lane & 7];
        sq = sh_q[lane & 7];
        #pragma unroll
        for (int o = 4; o; o >>= 1) {
            s  += __shfl_xor_sync(0xffffffffu, s,  o);
            sq += __shfl_xor_sync(0xffffffffu, sq, o);
        }
        if (lane == 0) { sh_s[0] = s; sh_q[0] = sq; }
    }
    __syncthreads();

    float mean = sh_s[0] * (1.0f / DD);
    float var  = sh_q[0] * (1.0f / DD) - mean * mean;
    float rstd = rsqrtf(var + 1e-5f);

    float4 wv = reinterpret_cast<const float4*>(w)[tid];
    float4 bv = reinterpret_cast<const float4*>(b)[tid];
    float4 o4;
    o4.x = (v.x - mean) * rstd * wv.x + bv.x;
    o4.y = (v.y - mean) * rstd * wv.y + bv.y;
    o4.z = (v.z - mean) * rstd * wv.z + bv.z;
    o4.w = (v.w - mean) * rstd * wv.w + bv.w;
    reinterpret_cast<float4*>(out + (size_t)row * DD)[tid] = o4;
}

// ---------------- SGEMM 128x128x8, 256 threads, 8x8/thread -------------------
// C[M,N] = A[M,K] @ B[K,N] + bias, with epilogue:
//   EPI=0: bias only;  EPI=1: bias + exact GELU;  EPI=2: bias + residual add
__device__ __forceinline__ float gelu_exact(float v) {
    return 0.5f * v * (1.0f + erff(v * 0.70710678118654752f));
}

template<int EPI>
__global__ __launch_bounds__(256)
void sgemm_k(const float* __restrict__ A, const float* __restrict__ B,
             const float* __restrict__ bias, const float* __restrict__ res,
             float* __restrict__ C, int M, int N, int K)
{
    __shared__ float As[8][128];
    __shared__ float Bs[8][128];

    int tid  = threadIdx.x;
    int row0 = blockIdx.y * 128;
    int col0 = blockIdx.x * 128;

    int arow = tid >> 1;            // 0..127
    int acol = (tid & 1) << 2;      // 0 or 4
    int brow = tid >> 5;            // 0..7
    int bcol = (tid & 31) << 2;     // 0..124

    const float* Ap = A + (size_t)(row0 + arow) * K + acol;
    const float* Bp = B + (size_t)brow * N + col0 + bcol;

    int ty = tid >> 4;              // 0..15
    int tx = tid & 15;              // 0..15

    float acc[8][8];
    #pragma unroll
    for (int i = 0; i < 8; i++)
        #pragma unroll
        for (int j = 0; j < 8; j++) acc[i][j] = 0.0f;

    for (int k0 = 0; k0 < K; k0 += 8) {
        float4 av = *reinterpret_cast<const float4*>(Ap + k0);
        float4 bv = *reinterpret_cast<const float4*>(Bp + (size_t)k0 * N);
        As[acol + 0][arow] = av.x;
        As[acol + 1][arow] = av.y;
        As[acol + 2][arow] = av.z;
        As[acol + 3][arow] = av.w;
        *reinterpret_cast<float4*>(&Bs[brow][bcol]) = bv;
        __syncthreads();

        #pragma unroll
        for (int kk = 0; kk < 8; kk++) {
            float4 a0 = reinterpret_cast<const float4*>(As[kk])[ty];
            float4 a1 = reinterpret_cast<const float4*>(As[kk])[16 + ty];
            float4 b0 = reinterpret_cast<const float4*>(Bs[kk])[tx];
            float4 b1 = reinterpret_cast<const float4*>(Bs[kk])[16 + tx];
            float ar[8] = {a0.x, a0.y, a0.z, a0.w, a1.x, a1.y, a1.z, a1.w};
            float br[8] = {b0.x, b0.y, b0.z, b0.w, b1.x, b1.y, b1.z, b1.w};
            #pragma unroll
            for (int i = 0; i < 8; i++)
                #pragma unroll
                for (int j = 0; j < 8; j++)
                    acc[i][j] += ar[i] * br[j];
        }
        __syncthreads();
    }

    // epilogue: rows {ty*4+i, 64+ty*4+i}, cols {tx*4.., 64+tx*4..}
    #pragma unroll
    for (int i = 0; i < 8; i++) {
        int r = row0 + ((i < 4) ? (ty * 4 + i) : (64 + ty * 4 + (i - 4)));
        #pragma unroll
        for (int jc = 0; jc < 2; jc++) {
            int c = col0 + jc * 64 + tx * 4;
            float4 bs = *reinterpret_cast<const float4*>(&bias[c]);
            float4 o;
            o.x = acc[i][jc * 4 + 0] + bs.x;
            o.y = acc[i][jc * 4 + 1] + bs.y;
            o.z = acc[i][jc * 4 + 2] + bs.z;
            o.w = acc[i][jc * 4 + 3] + bs.w;
            if (EPI == 1) {
                o.x = gelu_exact(o.x); o.y = gelu_exact(o.y);
                o.z = gelu_exact(o.z); o.w = gelu_exact(o.w);
            }
            if (EPI == 2) {
                float4 rv = *reinterpret_cast<const float4*>(&res[(size_t)r * N + c]);
                o.x += rv.x; o.y += rv.y; o.z += rv.z; o.w += rv.w;
            }
            *reinterpret_cast<float4*>(&C[(size_t)r * N + c]) = o;
        }
    }
}

// ---------------- Dilated windowed causal attention ---------------------------
// One warp per (b,h,i). Keys: j = i - 2t, t = 0..min(i,WIN)/2 (<=129 keys).
// Lane owns 2 of the 64 head dims. Online softmax.
__global__ __launch_bounds__(256)
void attn_kernel(const float* __restrict__ qkv, float* __restrict__ out)
{
    int gwarp = (blockIdx.x * blockDim.x + threadIdx.x) >> 5;   // 0..65535
    int lane  = threadIdx.x & 31;

    int i  = gwarp & (LL - 1);
    int bh = gwarp >> 11;          // 0..31
    int h  = bh & (HH - 1);
    int b  = bh >> 4;

    const float* base = qkv + (size_t)b * LL * 3 * DD + h * DHD + lane * 2;
    // q at row i, offset 0; k at +DD; v at +2*DD within the 3*DD row
    const float* qp = base + (size_t)i * (3 * DD);
    float2 q = *reinterpret_cast<const float2*>(qp);

    const float scale = 0.125f;    // 1/sqrt(64)
    float m = -1e30f, l = 0.0f, a0 = 0.0f, a1 = 0.0f;

    int tmax = (i < WIN ? i : WIN) >> 1;    // inclusive
    for (int t = 0; t <= tmax; t++) {
        int j = i - DIL * t;
        const float* kp = base + (size_t)j * (3 * DD) + DD;
        float2 kv = *reinterpret_cast<const float2*>(kp);
        float s = q.x * kv.x + q.y * kv.y;
        #pragma unroll
        for (int o = 16; o; o >>= 1) s += __shfl_xor_sync(0xffffffffu, s, o);
        s *= scale;

        float mn = fmaxf(m, s);
        float c  = __expf(m - mn);
        float p  = __expf(s - mn);
        float2 vv = *reinterpret_cast<const float2*>(kp + DD);
        l  = l * c + p;
        a0 = a0 * c + p * vv.x;
        a1 = a1 * c + p * vv.y;
        m  = mn;
    }
    float inv = 1.0f / l;
    float2 o2; o2.x = a0 * inv; o2.y = a1 * inv;
    *reinterpret_cast<float2*>(out + (size_t)(b * LL + i) * DD + h * DHD + lane * 2) = o2;
}

// ---------------- launch ------------------------------------------------------
extern "C" void kernel_launch(void* const* d_in, const int* in_sizes, int n_in,
                              void* d_out, int out_size)
{
    (void)in_sizes; (void)n_in; (void)out_size;
    const float* x    = (const float*)d_in[0];
    const float* n1w  = (const float*)d_in[1];
    const float* n1b  = (const float*)d_in[2];
    const float* qkvw = (const float*)d_in[3];
    const float* qkvb = (const float*)d_in[4];
    const float* outw = (const float*)d_in[5];
    const float* outb = (const float*)d_in[6];
    const float* n2w  = (const float*)d_in[7];
    const float* n2b  = (const float*)d_in[8];
    const float* fw1  = (const float*)d_in[9];
    const float* fb1  = (const float*)d_in[10];
    const float* fw2  = (const float*)d_in[11];
    const float* fb2  = (const float*)d_in[12];
    float* out = (float*)d_out;

    float *xn, *qkv, *attn, *y, *hbuf, *ffn;
    cudaGetSymbolAddress((void**)&xn,   g_xn);
    cudaGetSymbolAddress((void**)&qkv,  g_qkv);
    cudaGetSymbolAddress((void**)&attn, g_attn);
    cudaGetSymbolAddress((void**)&y,    g_y);
    cudaGetSymbolAddress((void**)&hbuf, g_h);
    cudaGetSymbolAddress((void**)&ffn,  g_ffn);

    // 1. LN1
    ln_kernel<<<ROWS, 256>>>(x, n1w, n1b, xn);
    // 2. QKV = xn @ qkv_w + qkv_b           [4096,1024]x[1024,3072]
    sgemm_k<0><<<dim3(3 * DD / 128, ROWS / 128), 256>>>(xn, qkvw, qkvb, nullptr, qkv,
                                                        ROWS, 3 * DD, DD);
    // 3. attention
    attn_kernel<<<(BB * HH * LL) / 8, 256>>>(qkv, attn);
    // 4. y = attn @ out_w + out_b + x       [4096,1024]x[1024,1024]
    sgemm_k<2><<<dim3(DD / 128, ROWS / 128), 256>>>(attn, outw, outb, x, y,
                                                    ROWS, DD, DD);
    // 5. LN2
    ln_kernel<<<ROWS, 256>>>(y, n2w, n2b, hbuf);
    // 6. ffn = gelu(h @ w1 + b1)            [4096,1024]x[1024,4096]
    sgemm_k<1><<<dim3(HID / 128, ROWS / 128), 256>>>(hbuf, fw1, fb1, nullptr, ffn,
                                                     ROWS, HID, DD);
    // 7. out = ffn @ w2 + b2 + y            [4096,4096]x[4096,1024]
    sgemm_k<2><<<dim3(DD / 128, ROWS / 128), 256>>>(ffn, fw2, fb2, y, out,
                                                    ROWS, DD, HID);
}

// round 3
// speedup vs baseline: 1.9713x; 1.9713x over previous
#include <cuda_runtime.h>
#include <math.h>
#include <stdint.h>

#define BB   2
#define LL   2048
#define DD   1024
#define HH   16
#define DHD  64
#define HID  4096
#define ROWS (BB*LL)
#define WIN  256
#define DIL  2

// ---------------- scratch (static device globals) ----------------------------
__device__ float g_xn  [ROWS * DD];
__device__ float g_qkv [ROWS * 3 * DD];
__device__ float g_attn[ROWS * DD];
__device__ float g_y   [ROWS * DD];
__device__ float g_h   [ROWS * DD];
__device__ float g_ffn [ROWS * HID];
// transposed weights, [N,K] K-major, tf32-rounded
__device__ float g_wqkv[3 * DD * DD];
__device__ float g_wout[DD * DD];
__device__ float g_w1  [HID * DD];
__device__ float g_w2  [DD * HID];

// ---------------- helpers -----------------------------------------------------
__device__ __forceinline__ uint32_t smem_u32(const void* p) {
    uint32_t a;
    asm("{ .reg .u64 t; cvta.to.shared.u64 t, %1; cvt.u32.u64 %0, t; }" : "=r"(a) : "l"(p));
    return a;
}
__device__ __forceinline__ float tf32r(float x) {
    uint32_t u;
    asm("cvt.rna.tf32.f32 %0, %1;" : "=r"(u) : "f"(x));
    return __uint_as_float(u);
}
__device__ __forceinline__ float gelu_exact(float v) {
    return 0.5f * v * (1.0f + erff(v * 0.70710678118654752f));
}
#define CP_ASYNC16(dst, src) \
    asm volatile("cp.async.cg.shared.global [%0], [%1], 16;" :: "r"(dst), "l"(src))
#define CP_COMMIT()  asm volatile("cp.async.commit_group;" ::: "memory")
#define CP_WAIT1()   asm volatile("cp.async.wait_group 1;" ::: "memory")

__device__ __forceinline__ void mma_tf32_16n8k8(float* c, const float* a, const float* b) {
    asm volatile(
        "mma.sync.aligned.m16n8k8.row.col.f32.tf32.tf32.f32 "
        "{%0,%1,%2,%3}, {%4,%5,%6,%7}, {%8,%9}, {%0,%1,%2,%3};"
        : "+f"(c[0]), "+f"(c[1]), "+f"(c[2]), "+f"(c[3])
        : "r"(__float_as_uint(a[0])), "r"(__float_as_uint(a[1])),
          "r"(__float_as_uint(a[2])), "r"(__float_as_uint(a[3])),
          "r"(__float_as_uint(b[0])), "r"(__float_as_uint(b[1])));
}

// ---------------- transpose + tf32 round: src[R][C] -> dst[C][R] --------------
__global__ __launch_bounds__(256)
void transpose_k(const float* __restrict__ S, float* __restrict__ T, int R, int C)
{
    __shared__ float t[32][33];
    int c0 = blockIdx.x * 32, r0 = blockIdx.y * 32;
    int tx = threadIdx.x, ty = threadIdx.y;
    #pragma unroll
    for (int i = 0; i < 32; i += 8)
        t[ty + i][tx] = S[(size_t)(r0 + ty + i) * C + c0 + tx];
    __syncthreads();
    #pragma unroll
    for (int i = 0; i < 32; i += 8)
        T[(size_t)(c0 + ty + i) * R + r0 + tx] = tf32r(t[tx][ty + i]);
}

// ---------------- LayerNorm (output tf32-rounded: feeds GEMMs only) ----------
__global__ __launch_bounds__(256)
void ln_kernel(const float* __restrict__ x, const float* __restrict__ w,
               const float* __restrict__ b, float* __restrict__ out)
{
    int row = blockIdx.x, tid = threadIdx.x;
    float4 v = reinterpret_cast<const float4*>(x + (size_t)row * DD)[tid];
    float s  = v.x + v.y + v.z + v.w;
    float sq = v.x*v.x + v.y*v.y + v.z*v.z + v.w*v.w;
    __shared__ float sh_s[8], sh_q[8];
    #pragma unroll
    for (int o = 16; o; o >>= 1) {
        s  += __shfl_xor_sync(0xffffffffu, s,  o);
        sq += __shfl_xor_sync(0xffffffffu, sq, o);
    }
    int warp = tid >> 5, lane = tid & 31;
    if (lane == 0) { sh_s[warp] = s; sh_q[warp] = sq; }
    __syncthreads();
    if (warp == 0) {
        s = sh_s[lane & 7]; sq = sh_q[lane & 7];
        #pragma unroll
        for (int o = 4; o; o >>= 1) {
            s  += __shfl_xor_sync(0xffffffffu, s,  o);
            sq += __shfl_xor_sync(0xffffffffu, sq, o);
        }
        if (lane == 0) { sh_s[0] = s; sh_q[0] = sq; }
    }
    __syncthreads();
    float mean = sh_s[0] * (1.0f / DD);
    float var  = sh_q[0] * (1.0f / DD) - mean * mean;
    float rstd = rsqrtf(var + 1e-5f);
    float4 wv = reinterpret_cast<const float4*>(w)[tid];
    float4 bv = reinterpret_cast<const float4*>(b)[tid];
    float4 o4;
    o4.x = tf32r((v.x - mean) * rstd * wv.x + bv.x);
    o4.y = tf32r((v.y - mean) * rstd * wv.y + bv.y);
    o4.z = tf32r((v.z - mean) * rstd * wv.z + bv.z);
    o4.w = tf32r((v.w - mean) * rstd * wv.w + bv.w);
    reinterpret_cast<float4*>(out + (size_t)row * DD)[tid] = o4;
}

// ---------------- TF32 tensor GEMM: C[M,N] = A[M,K] @ Bt[N,K]^T + epilogue ----
// EPI=0: +bias;  EPI=1: +bias, GELU, tf32-round;  EPI=2: +bias, +residual
#define BKF     32                  // K floats per stage
#define STRF    36                  // padded row stride (floats)
#define TILEB   (128 * STRF * 4)    // 18432 B per operand tile
#define STAGEB  (2 * TILEB)         // 36864 B per stage
#define NSTG    3
#define GEMM_SMEM (NSTG * STAGEB)   // 110592 B

template<int EPI>
__global__ __launch_bounds__(256)
void tc_gemm(const float* __restrict__ A, const float* __restrict__ Bt,
             const float* __restrict__ bias, const float* __restrict__ res,
             float* __restrict__ C, int M, int N, int K)
{
    extern __shared__ float smem[];
    uint32_t sbase = smem_u32(smem);

    int tid = threadIdx.x, lane = tid & 31, wid = tid >> 5;
    int g = lane >> 2, tig = lane & 3;
    int wr0 = (wid & 3) << 5;            // warp row offset in tile (0..96)
    int wc0 = (wid >> 2) << 6;           // warp col offset (0/64)
    int row0 = blockIdx.y << 7, col0 = blockIdx.x << 7;

    // global->smem mapping: thread covers row lm, k-half lh (16 floats), 4x16B
    int lm = tid >> 1, lh = tid & 1;
    const float* ga = A  + (size_t)(row0 + lm) * K + lh * 16;
    const float* gb = Bt + (size_t)(col0 + lm) * K + lh * 16;
    uint32_t soff = lm * (STRF * 4) + lh * 64;

    float acc[2][8][4];
    #pragma unroll
    for (int mt = 0; mt < 2; mt++)
        #pragma unroll
        for (int nt = 0; nt < 8; nt++)
            #pragma unroll
            for (int q = 0; q < 4; q++) acc[mt][nt][q] = 0.0f;

    int NC = K >> 5;

    // prologue: stages 0,1
    #pragma unroll
    for (int p = 0; p < 2; p++) {
        uint32_t a0 = sbase + p * STAGEB + soff;
        const float* pa = ga + p * BKF;
        const float* pb = gb + p * BKF;
        #pragma unroll
        for (int j = 0; j < 4; j++) {
            CP_ASYNC16(a0 + j * 16,         pa + j * 4);
            CP_ASYNC16(a0 + TILEB + j * 16, pb + j * 4);
        }
        CP_COMMIT();
    }

    for (int it = 0; it < NC; it++) {
        CP_WAIT1();
        __syncthreads();

        int nxt = it + 2;
        if (nxt < NC) {
            int st = nxt % NSTG;
            uint32_t a0 = sbase + st * STAGEB + soff;
            const float* pa = ga + nxt * BKF;
            const float* pb = gb + nxt * BKF;
            #pragma unroll
            for (int j = 0; j < 4; j++) {
                CP_ASYNC16(a0 + j * 16,         pa + j * 4);
                CP_ASYNC16(a0 + TILEB + j * 16, pb + j * 4);
            }
        }
        CP_COMMIT();

        // compute stage it%3
        const float* As = smem + (size_t)(it % NSTG) * (STAGEB / 4);
        const float* Bs = As + (TILEB / 4);
        #pragma unroll
        for (int ks = 0; ks < 4; ks++) {
            int k0 = ks * 8;
            float a[2][4];
            #pragma unroll
            for (int mt = 0; mt < 2; mt++) {
                int m = wr0 + mt * 16 + g;
                a[mt][0] = As[m * STRF + k0 + tig];
                a[mt][1] = As[(m + 8) * STRF + k0 + tig];
                a[mt][2] = As[m * STRF + k0 + tig + 4];
                a[mt][3] = As[(m + 8) * STRF + k0 + tig + 4];
            }
            float b[8][2];
            #pragma unroll
            for (int nt = 0; nt < 8; nt++) {
                int n = wc0 + nt * 8 + g;
                b[nt][0] = Bs[n * STRF + k0 + tig];
                b[nt][1] = Bs[n * STRF + k0 + tig + 4];
            }
            #pragma unroll
            for (int mt = 0; mt < 2; mt++)
                #pragma unroll
                for (int nt = 0; nt < 8; nt++)
                    mma_tf32_16n8k8(acc[mt][nt], a[mt], b[nt]);
        }
    }

    // epilogue
    #pragma unroll
    for (int mt = 0; mt < 2; mt++) {
        int r1 = row0 + wr0 + mt * 16 + g;
        int r2 = r1 + 8;
        #pragma unroll
        for (int nt = 0; nt < 8; nt++) {
            int col = col0 + wc0 + nt * 8 + tig * 2;
            float2 bv = *reinterpret_cast<const float2*>(bias + col);
            float o0 = acc[mt][nt][0] + bv.x;
            float o1 = acc[mt][nt][1] + bv.y;
            float o2 = acc[mt][nt][2] + bv.x;
            float o3 = acc[mt][nt][3] + bv.y;
            if (EPI == 1) {
                o0 = tf32r(gelu_exact(o0)); o1 = tf32r(gelu_exact(o1));
                o2 = tf32r(gelu_exact(o2)); o3 = tf32r(gelu_exact(o3));
            }
            if (EPI == 2) {
                float2 rv1 = *reinterpret_cast<const float2*>(res + (size_t)r1 * N + col);
                float2 rv2 = *reinterpret_cast<const float2*>(res + (size_t)r2 * N + col);
                o0 += rv1.x; o1 += rv1.y; o2 += rv2.x; o3 += rv2.y;
            }
            float2 w1v; w1v.x = o0; w1v.y = o1;
            float2 w2v; w2v.x = o2; w2v.y = o3;
            *reinterpret_cast<float2*>(C + (size_t)r1 * N + col) = w1v;
            *reinterpret_cast<float2*>(C + (size_t)r2 * N + col) = w2v;
        }
    }
}

// ---------------- dilated windowed causal attention ---------------------------
__global__ __launch_bounds__(256)
void attn_kernel(const float* __restrict__ qkv, float* __restrict__ out)
{
    int gwarp = (blockIdx.x * blockDim.x + threadIdx.x) >> 5;
    int lane  = threadIdx.x & 31;
    int i  = gwarp & (LL - 1);
    int bh = gwarp >> 11;
    int h  = bh & (HH - 1);
    int b  = bh >> 4;

    const float* base = qkv + (size_t)b * LL * 3 * DD + h * DHD + lane * 2;
    float2 q = *reinterpret_cast<const float2*>(base + (size_t)i * (3 * DD));

    const float scale = 0.125f;
    float m = -1e30f, l = 0.0f, a0 = 0.0f, a1 = 0.0f;
    int tmax = (i < WIN ? i : WIN) >> 1;
    for (int t = 0; t <= tmax; t++) {
        int j = i - DIL * t;
        const float* kp = base + (size_t)j * (3 * DD) + DD;
        float2 kv = *reinterpret_cast<const float2*>(kp);
        float sdot = q.x * kv.x + q.y * kv.y;
        #pragma unroll
        for (int o = 16; o; o >>= 1) sdot += __shfl_xor_sync(0xffffffffu, sdot, o);
        sdot *= scale;
        float mn = fmaxf(m, sdot);
        float c  = __expf(m - mn);
        float p  = __expf(sdot - mn);
        float2 vv = *reinterpret_cast<const float2*>(kp + DD);
        l  = l * c + p;
        a0 = a0 * c + p * vv.x;
        a1 = a1 * c + p * vv.y;
        m  = mn;
    }
    float inv = 1.0f / l;
    float2 o2;
    o2.x = tf32r(a0 * inv);   // feeds out-proj GEMM
    o2.y = tf32r(a1 * inv);
    *reinterpret_cast<float2*>(out + (size_t)(b * LL + i) * DD + h * DHD + lane * 2) = o2;
}

// ---------------- launch ------------------------------------------------------
extern "C" void kernel_launch(void* const* d_in, const int* in_sizes, int n_in,
                              void* d_out, int out_size)
{
    (void)in_sizes; (void)n_in; (void)out_size;
    const float* x    = (const float*)d_in[0];
    const float* n1w  = (const float*)d_in[1];
    const float* n1b  = (const float*)d_in[2];
    const float* qkvw = (const float*)d_in[3];
    const float* qkvb = (const float*)d_in[4];
    const float* outw = (const float*)d_in[5];
    const float* outb = (const float*)d_in[6];
    const float* n2w  = (const float*)d_in[7];
    const float* n2b  = (const float*)d_in[8];
    const float* fw1  = (const float*)d_in[9];
    const float* fb1  = (const float*)d_in[10];
    const float* fw2  = (const float*)d_in[11];
    const float* fb2  = (const float*)d_in[12];
    float* out = (float*)d_out;

    float *xn, *qkv, *attn, *y, *hbuf, *ffn, *wq, *wo, *w1, *w2;
    cudaGetSymbolAddress((void**)&xn,   g_xn);
    cudaGetSymbolAddress((void**)&qkv,  g_qkv);
    cudaGetSymbolAddress((void**)&attn, g_attn);
    cudaGetSymbolAddress((void**)&y,    g_y);
    cudaGetSymbolAddress((void**)&hbuf, g_h);
    cudaGetSymbolAddress((void**)&ffn,  g_ffn);
    cudaGetSymbolAddress((void**)&wq,   g_wqkv);
    cudaGetSymbolAddress((void**)&wo,   g_wout);
    cudaGetSymbolAddress((void**)&w1,   g_w1);
    cudaGetSymbolAddress((void**)&w2,   g_w2);

    cudaFuncSetAttribute(tc_gemm<0>, cudaFuncAttributeMaxDynamicSharedMemorySize, GEMM_SMEM);
    cudaFuncSetAttribute(tc_gemm<1>, cudaFuncAttributeMaxDynamicSharedMemorySize, GEMM_SMEM);
    cudaFuncSetAttribute(tc_gemm<2>, cudaFuncAttributeMaxDynamicSharedMemorySize, GEMM_SMEM);

    dim3 tb(32, 8);
    transpose_k<<<dim3(3 * DD / 32, DD / 32), tb>>>(qkvw, wq, DD, 3 * DD);
    transpose_k<<<dim3(DD / 32, DD / 32),     tb>>>(outw, wo, DD, DD);
    transpose_k<<<dim3(HID / 32, DD / 32),    tb>>>(fw1,  w1, DD, HID);
    transpose_k<<<dim3(DD / 32, HID / 32),    tb>>>(fw2,  w2, HID, DD);

    // 1. LN1 (tf32-rounded output)
    ln_kernel<<<ROWS, 256>>>(x, n1w, n1b, xn);
    // 2. QKV = xn @ qkv_w + qkv_b   (fp32 output for attention)
    tc_gemm<0><<<dim3(3 * DD / 128, ROWS / 128), 256, GEMM_SMEM>>>(
        xn, wq, qkvb, nullptr, qkv, ROWS, 3 * DD, DD);
    // 3. attention (tf32-rounded output)
    attn_kernel<<<(BB * HH * LL) / 8, 256>>>(qkv, attn);
    // 4. y = attn @ out_w + out_b + x
    tc_gemm<2><<<dim3(DD / 128, ROWS / 128), 256, GEMM_SMEM>>>(
        attn, wo, outb, x, y, ROWS, DD, DD);
    // 5. LN2 (tf32-rounded output)
    ln_kernel<<<ROWS, 256>>>(y, n2w, n2b, hbuf);
    // 6. ffn = gelu(h @ w1 + b1)    (tf32-rounded output)
    tc_gemm<1><<<dim3(HID / 128, ROWS / 128), 256, GEMM_SMEM>>>(
        hbuf, w1, fb1, nullptr, ffn, ROWS, HID, DD);
    // 7. out = ffn @ w2 + b2 + y
    tc_gemm<2><<<dim3(DD / 128, ROWS / 128), 256, GEMM_SMEM>>>(
        ffn, w2, fb2, y, out, ROWS, DD, HID);
}